// round 11
// baseline (speedup 1.0000x reference)
#include <cuda_runtime.h>
#include <cuda_bf16.h>

#define NB 2
#define NN 2048
#define NF 256
#define NH 8
#define NO 32

typedef unsigned long long ull;

// ---------------- f32x2 packed-math helpers (sm_103a FFMA2 path) --------------
__device__ __forceinline__ void ffma2(ull& d, ull a, ull b) {
    asm("fma.rn.f32x2 %0, %1, %2, %0;" : "+l"(d) : "l"(a), "l"(b));
}
__device__ __forceinline__ float2 unpack2(ull v) {
    float2 r;
    asm("mov.b64 {%0, %1}, %2;" : "=f"(r.x), "=f"(r.y) : "l"(v));
    return r;
}

// ---------------- cp.async helpers --------------------------------------------
__device__ __forceinline__ void cp16(const void* smem_dst, const void* gsrc) {
    unsigned d = (unsigned)__cvta_generic_to_shared(smem_dst);
    asm volatile("cp.async.cg.shared.global [%0], [%1], 16;" :: "r"(d), "l"(gsrc));
}
#define CP_COMMIT() asm volatile("cp.async.commit_group;")
#define CP_WAIT0()  asm volatile("cp.async.wait_group 0;")
#define CP_WAIT1()  asm volatile("cp.async.wait_group 1;")

// ---------------- scratch (device globals; no allocation allowed) -------------
__device__ __align__(128) float    g_h  [NB*NN*NF];  // layer input / stage-B output
__device__ __align__(128) float    g_hA [NB*NN*NF];  // stage-A attention output
__device__ __align__(128) float    g_Wh [NB*NN*NF];  // projected features, row-major
__device__ __align__(128) float    g_WhT[NB*NF*NN];  // projected features, col-major
__device__ __align__(128) float    g_s1[NB*NH*NN];
__device__ __align__(128) float    g_s2[NB*NH*NN];
__device__ __align__(128) unsigned g_bm[NB*NN*(NN/32)];  // adjacency bitmask

// ---------------- adjacency -> bitmask (runs once) ----------------------------
__global__ void bm_kernel(const int* __restrict__ adj) {
    int wid  = blockIdx.x * 8 + (threadIdx.x >> 5);
    int lane = threadIdx.x & 31;
    int word = wid & 63;
    int row  = wid >> 6;                       // b*NN + i
    int j = word * 32 + lane;
    int a = adj[(size_t)row * NN + j];
    unsigned bits = __ballot_sync(0xffffffffu, a != 0);
    if (lane == 0) g_bm[wid] = bits;
}

// ---------------- GEMM: Wh/WhT = A[M,256] @ B[256,256] ------------------------
// asel: 0 -> Aext (x), 1 -> g_h, 2 -> g_hA
// bmode 0: B = W_heads[l] head-packed on the fly; bmode 1: B = Bsrc (plain)
__global__ void gemm_kernel(const float* __restrict__ Aext,
                            const float* __restrict__ Bsrc,
                            int asel, int bmode) {
    const float* A = (asel == 0) ? Aext : (asel == 1 ? g_h : g_hA);
    __shared__ __align__(16) float Ast[16][68];   // [k][m], padded
    __shared__ __align__(16) float Bs [16][64];   // [k][n]
    int tid = threadIdx.x;
    int tx = tid & 15, ty = tid >> 4;
    int mbase = blockIdx.y * 64, nbase = blockIdx.x * 64;
    float acc[4][4];
    #pragma unroll
    for (int i = 0; i < 4; i++)
        #pragma unroll
        for (int j = 0; j < 4; j++) acc[i][j] = 0.f;

    int am = tid >> 2, ak = (tid & 3) * 4;
    int bk = tid >> 4, bn = (tid & 15) * 4;
    int c0 = nbase + bn, hh = c0 >> 5, cc = c0 & 31;

    for (int kk = 0; kk < NF; kk += 16) {
        float4 av = *(const float4*)&A[(size_t)(mbase + am) * NF + kk + ak];
        float4 bv;
        if (bmode == 0)   // W_heads[l][h][f][o] with h=c>>5, o=c&31 (cc mult of 4)
            bv = *(const float4*)&Bsrc[((size_t)hh * NF + kk + bk) * NO + cc];
        else
            bv = *(const float4*)&Bsrc[(size_t)(kk + bk) * NF + c0];
        Ast[ak + 0][am] = av.x; Ast[ak + 1][am] = av.y;
        Ast[ak + 2][am] = av.z; Ast[ak + 3][am] = av.w;
        *(float4*)&Bs[bk][bn] = bv;
        __syncthreads();
        #pragma unroll
        for (int k = 0; k < 16; k++) {
            float4 a = *(const float4*)&Ast[k][ty * 4];
            float4 b = *(const float4*)&Bs [k][tx * 4];
            acc[0][0] += a.x * b.x; acc[0][1] += a.x * b.y;
            acc[0][2] += a.x * b.z; acc[0][3] += a.x * b.w;
            acc[1][0] += a.y * b.x; acc[1][1] += a.y * b.y;
            acc[1][2] += a.y * b.z; acc[1][3] += a.y * b.w;
            acc[2][0] += a.z * b.x; acc[2][1] += a.z * b.y;
            acc[2][2] += a.z * b.z; acc[2][3] += a.z * b.w;
            acc[3][0] += a.w * b.x; acc[3][1] += a.w * b.y;
            acc[3][2] += a.w * b.z; acc[3][3] += a.w * b.w;
        }
        __syncthreads();
    }
    int bb = mbase >> 11, rowb = mbase & (NN - 1);
    #pragma unroll
    for (int i = 0; i < 4; i++) {
        *(float4*)&g_Wh[(size_t)(mbase + ty * 4 + i) * NF + nbase + tx * 4] =
            make_float4(acc[i][0], acc[i][1], acc[i][2], acc[i][3]);
    }
    // transposed store: thread holds a 4x4 block; write 4 float4s along n (col j)
    #pragma unroll
    for (int j = 0; j < 4; j++) {
        *(float4*)&g_WhT[((size_t)bb * NF + nbase + tx * 4 + j) * NN
                         + rowb + ty * 4] =
            make_float4(acc[0][j], acc[1][j], acc[2][j], acc[3][j]);
    }
}

// ---------------- s1/s2 for the 8-head stage ----------------------------------
__global__ void sheads_kernel(const float* __restrict__ aheads, int l) {
    int w = threadIdx.x >> 5, lane = threadIdx.x & 31;
    int row = blockIdx.x * 8 + w;          // b*NN + n
    int b = row >> 11, n = row & (NN - 1);
    #pragma unroll
    for (int h = 0; h < NH; h++) {
        float v  = g_Wh[(size_t)row * NF + h * NO + lane];
        float a1 = aheads[((size_t)l * NH + h) * 2 * NO + lane];
        float a2 = aheads[((size_t)l * NH + h) * 2 * NO + NO + lane];
        float p1 = v * a1, p2 = v * a2;
        #pragma unroll
        for (int off = 16; off; off >>= 1) {
            p1 += __shfl_xor_sync(0xffffffffu, p1, off);
            p2 += __shfl_xor_sync(0xffffffffu, p2, off);
        }
        if (lane == 0) {
            g_s1[(b * NH + h) * NN + n] = p1;
            g_s2[(b * NH + h) * NN + n] = p2;
        }
    }
}

// ---------------- s1/s2 for the single-head out stage -------------------------
__global__ void sout_kernel(const float* __restrict__ aout, int l) {
    int w = threadIdx.x >> 5, lane = threadIdx.x & 31;
    int row = blockIdx.x * 8 + w;          // b*NN + n
    float p1 = 0.f, p2 = 0.f;
    #pragma unroll
    for (int k = 0; k < NF / 32; k++) {
        float v = g_Wh[(size_t)row * NF + k * 32 + lane];
        p1 += v * aout[(size_t)l * 2 * NF + k * 32 + lane];
        p2 += v * aout[(size_t)l * 2 * NF + NF + k * 32 + lane];
    }
    #pragma unroll
    for (int off = 16; off; off >>= 1) {
        p1 += __shfl_xor_sync(0xffffffffu, p1, off);
        p2 += __shfl_xor_sync(0xffffffffu, p2, off);
    }
    if (lane == 0) { g_s1[row] = p1; g_s2[row] = p2; }
}

// ---------------- fused masked-softmax attention + P@V + elu -----------------
// v7 = v6 with all micro-GEMM smem operands read as ulonglong2 (LDS.128):
// pk broadcast pairs 64->32 instructions AND wavefronts per chunk; vj pairs
// 16->8 instructions (bytes unchanged). No structural change.
// grid (64, 8, NB), block 256.
#define JT  128
#define RPW 4
#define AW  8

__global__ void __launch_bounds__(256)
attn_kernel(float* __restrict__ oext, int osel,
            int spb, int symul, int elu2) {
    __shared__ __align__(16) float4 VT[2][1024];   // [buf][o*32 + (jc^o)]
    __shared__ __align__(16) float  s2t[2][JT];
    __shared__ __align__(16) float  ps[AW][RPW][32];
    __shared__ float red[AW];

    float* out = (osel == 0) ? g_hA : (osel == 1 ? g_h : oext);
    int b = blockIdx.z, y = blockIdx.y;
    int tid = threadIdx.x;
    int w = tid >> 5, lane = tid & 31;
    int vb = y * NO;
    int sidx = b * spb + y * symul;
    const float* s1p = g_s1 + (size_t)sidx * NN;
    const float* s2p = g_s2 + (size_t)sidx * NN;

    // fused m2: block-local max of s2 (any upper bound is valid for softmax)
    float mloc = -3.0e38f;
    for (int i = tid; i < NN; i += 256) mloc = fmaxf(mloc, s2p[i]);
    #pragma unroll
    for (int off = 16; off; off >>= 1)
        mloc = fmaxf(mloc, __shfl_xor_sync(0xffffffffu, mloc, off));
    if (lane == 0) red[w] = mloc;
    __syncthreads();
    float m2 = red[0];
    #pragma unroll
    for (int i = 1; i < AW; i++) m2 = fmaxf(m2, red[i]);

    int row0 = blockIdx.x * (AW * RPW) + w * RPW;

    float s1r[RPW], cir[RPW], lsum[RPW];
    ull acc2[RPW];
    const uint4* bmq[RPW];
    #pragma unroll
    for (int r = 0; r < RPW; r++) {
        s1r[r] = s1p[row0 + r];
        float t = s1r[r] + m2;
        cir[r] = fmaxf(t, 0.2f * t);
        acc2[r] = 0ull; lsum[r] = 0.f;
        bmq[r] = (const uint4*)(g_bm + ((size_t)(b * NN + row0 + r) << 6));
    }
    const float* WT = g_WhT + ((size_t)(b * NF + vb)) * NN;

    // ---- prologue: async-load tile 0 ----
    {
        #pragma unroll
        for (int k = 0; k < 4; k++) {
            int q = tid + 256 * k, o = q >> 5, jc = q & 31;
            cp16(&VT[0][(o << 5) | (jc ^ o)], WT + (size_t)o * NN + (jc << 2));
        }
        if (tid < 32) cp16(&s2t[0][tid * 4], s2p + tid * 4);
        CP_COMMIT();
    }

    for (int it = 0; it < NN / JT; it++) {
        int buf = it & 1;
        if (it + 1 < NN / JT) {       // prefetch next tile into alt buffer
            int jn = (it + 1) * JT;
            #pragma unroll
            for (int k = 0; k < 4; k++) {
                int q = tid + 256 * k, o = q >> 5, jc = q & 31;
                cp16(&VT[buf ^ 1][(o << 5) | (jc ^ o)],
                     WT + (size_t)o * NN + jn + (jc << 2));
            }
            if (tid < 32) cp16(&s2t[buf ^ 1][tid * 4], s2p + jn + tid * 4);
            CP_COMMIT();
            CP_WAIT1();
        } else {
            CP_WAIT0();
        }
        __syncthreads();

        uint4 mq[RPW];
        #pragma unroll
        for (int r = 0; r < RPW; r++) mq[r] = __ldg(&bmq[r][it]);

        #pragma unroll
        for (int c = 0; c < 4; c++) {
            float s2v = s2t[buf][c * 32 + lane];
            #pragma unroll
            for (int r = 0; r < RPW; r++) {
                unsigned mw = (c == 0) ? mq[r].x : (c == 1) ? mq[r].y
                            : (c == 2) ? mq[r].z : mq[r].w;
                float x = s1r[r] + s2v;
                float e = fmaxf(x, 0.2f * x);           // leakyrelu(0.2)
                float p = ((mw >> lane) & 1u) ? __expf(e - cir[r]) : 0.f;
                lsum[r] += p;
                ps[w][r][lane] = p;
            }
            __syncwarp();
            #pragma unroll
            for (int k4 = 0; k4 < 8; k4++) {
                ulonglong2 vj = *(const ulonglong2*)
                    &VT[buf][(lane << 5) | ((c * 8 + k4) ^ lane)];
                #pragma unroll
                for (int r = 0; r < RPW; r++) {
                    ulonglong2 pk = *(const ulonglong2*)&ps[w][r][k4 * 4];
                    ffma2(acc2[r], pk.x, vj.x);
                    ffma2(acc2[r], pk.y, vj.y);
                }
            }
            __syncwarp();
        }
        __syncthreads();
    }

    #pragma unroll
    for (int r = 0; r < RPW; r++) {
        float l = lsum[r];
        #pragma unroll
        for (int off = 16; off; off >>= 1)
            l += __shfl_xor_sync(0xffffffffu, l, off);
        float2 ap = unpack2(acc2[r]);
        float v = (ap.x + ap.y) / l;
        v = (v > 0.f) ? v : (__expf(v) - 1.f);          // elu
        if (elu2) v = (v > 0.f) ? v : (__expf(v) - 1.f); // second elu (out stage)
        out[(size_t)(b * NN + row0 + r) * NF + vb + lane] = v;
    }
}

// ---------------- launch ------------------------------------------------------
extern "C" void kernel_launch(void* const* d_in, const int* in_sizes, int n_in,
                              void* d_out, int out_size) {
    const float* x       = (const float*)d_in[0];
    const int*   adj     = (const int*)  d_in[1];
    const float* W_heads = (const float*)d_in[2];
    const float* a_heads = (const float*)d_in[3];
    const float* W_out   = (const float*)d_in[4];
    const float* a_out   = (const float*)d_in[5];
    float* out = (float*)d_out;

    for (int l = 0; l < 3; l++) {
        // ---- stage A: 8-head GAT ----
        gemm_kernel<<<dim3(4, NB * NN / 64), 256>>>(
            l == 0 ? x : nullptr, W_heads + (size_t)l * NH * NF * NO,
            l == 0 ? 0 : 1, 0);
        sheads_kernel<<<NB * NN / 8, 256>>>(a_heads, l);
        if (l == 0) bm_kernel<<<NB * NN * 64 / 8, 256>>>(adj);
        attn_kernel<<<dim3(NN / (AW * RPW), 8, NB), 256>>>(nullptr, 0, NH, 1, 0);

        // ---- stage B: single-head out GAT (+extra elu) ----
        gemm_kernel<<<dim3(4, NB * NN / 64), 256>>>(
            nullptr, W_out + (size_t)l * NF * NF, 2, 1);
        sout_kernel<<<NB * NN / 8, 256>>>(a_out, l);
        attn_kernel<<<dim3(NN / (AW * RPW), 8, NB), 256>>>(
            l == 2 ? out : nullptr, l == 2 ? 2 : 1, 1, 0, 1);
    }
}

// round 14
// speedup vs baseline: 1.0687x; 1.0687x over previous
#include <cuda_runtime.h>
#include <cuda_bf16.h>

#define NB 2
#define NN 2048
#define NF 256
#define NH 8
#define NO 32

typedef unsigned long long ull;

// ---------------- f32x2 packed-math helpers (sm_103a FFMA2 path) --------------
__device__ __forceinline__ void ffma2(ull& d, ull a, ull b) {
    asm("fma.rn.f32x2 %0, %1, %2, %0;" : "+l"(d) : "l"(a), "l"(b));
}
__device__ __forceinline__ void fadd2(ull& d, ull a) {
    asm("add.rn.f32x2 %0, %1, %0;" : "+l"(d) : "l"(a));
}
__device__ __forceinline__ ull pack2(float x, float y) {
    ull r;
    asm("mov.b64 %0, {%1, %2};" : "=l"(r) : "f"(x), "f"(y));
    return r;
}
__device__ __forceinline__ float2 unpack2(ull v) {
    float2 r;
    asm("mov.b64 {%0, %1}, %2;" : "=f"(r.x), "=f"(r.y) : "l"(v));
    return r;
}

// ---------------- cp.async helpers --------------------------------------------
__device__ __forceinline__ void cp16(const void* smem_dst, const void* gsrc) {
    unsigned d = (unsigned)__cvta_generic_to_shared(smem_dst);
    asm volatile("cp.async.cg.shared.global [%0], [%1], 16;" :: "r"(d), "l"(gsrc));
}
#define CP_COMMIT() asm volatile("cp.async.commit_group;")
#define CP_WAIT0()  asm volatile("cp.async.wait_group 0;")
#define CP_WAIT1()  asm volatile("cp.async.wait_group 1;")

// ---------------- scratch (device globals; no allocation allowed) -------------
__device__ __align__(128) float    g_h [NB*NN*NF];   // layer input / stage-B output
__device__ __align__(128) float    g_hA[NB*NN*NF];   // stage-A attention output
__device__ __align__(128) float    g_Wh[NB*NN*NF];   // projected features (V), row-major
__device__ __align__(128) float    g_s1[NB*NH*NN];
__device__ __align__(128) float    g_s2[NB*NH*NN];
__device__ __align__(128) unsigned g_bm[NB*NN*(NN/32)];  // adjacency bitmask

// ---------------- adjacency -> bitmask (runs once) ----------------------------
__global__ void bm_kernel(const int* __restrict__ adj) {
    int wid  = blockIdx.x * 8 + (threadIdx.x >> 5);
    int lane = threadIdx.x & 31;
    int word = wid & 63;
    int row  = wid >> 6;                       // b*NN + i
    int j = word * 32 + lane;
    int a = adj[(size_t)row * NN + j];
    unsigned bits = __ballot_sync(0xffffffffu, a != 0);
    if (lane == 0) g_bm[wid] = bits;
}

// ---------------- GEMM: g_Wh = A[M,256] @ B[256,256] --------------------------
// asel: 0 -> Aext (x), 1 -> g_h, 2 -> g_hA
// bmode 0: B = W_heads[l] head-packed on the fly; bmode 1: B = Bsrc (plain)
__global__ void gemm_kernel(const float* __restrict__ Aext,
                            const float* __restrict__ Bsrc,
                            int asel, int bmode) {
    const float* A = (asel == 0) ? Aext : (asel == 1 ? g_h : g_hA);
    __shared__ __align__(16) float Ast[16][68];   // [k][m], padded
    __shared__ __align__(16) float Bs [16][64];   // [k][n]
    int tid = threadIdx.x;
    int tx = tid & 15, ty = tid >> 4;
    int mbase = blockIdx.y * 64, nbase = blockIdx.x * 64;
    float acc[4][4];
    #pragma unroll
    for (int i = 0; i < 4; i++)
        #pragma unroll
        for (int j = 0; j < 4; j++) acc[i][j] = 0.f;

    int am = tid >> 2, ak = (tid & 3) * 4;
    int bk = tid >> 4, bn = (tid & 15) * 4;
    int c0 = nbase + bn, hh = c0 >> 5, cc = c0 & 31;

    for (int kk = 0; kk < NF; kk += 16) {
        float4 av = *(const float4*)&A[(size_t)(mbase + am) * NF + kk + ak];
        float4 bv;
        if (bmode == 0)   // W_heads[l][h][f][o] with h=c>>5, o=c&31 (cc mult of 4)
            bv = *(const float4*)&Bsrc[((size_t)hh * NF + kk + bk) * NO + cc];
        else
            bv = *(const float4*)&Bsrc[(size_t)(kk + bk) * NF + c0];
        Ast[ak + 0][am] = av.x; Ast[ak + 1][am] = av.y;
        Ast[ak + 2][am] = av.z; Ast[ak + 3][am] = av.w;
        *(float4*)&Bs[bk][bn] = bv;
        __syncthreads();
        #pragma unroll
        for (int k = 0; k < 16; k++) {
            float4 a = *(const float4*)&Ast[k][ty * 4];
            float4 b = *(const float4*)&Bs [k][tx * 4];
            acc[0][0] += a.x * b.x; acc[0][1] += a.x * b.y;
            acc[0][2] += a.x * b.z; acc[0][3] += a.x * b.w;
            acc[1][0] += a.y * b.x; acc[1][1] += a.y * b.y;
            acc[1][2] += a.y * b.z; acc[1][3] += a.y * b.w;
            acc[2][0] += a.z * b.x; acc[2][1] += a.z * b.y;
            acc[2][2] += a.z * b.z; acc[2][3] += a.z * b.w;
            acc[3][0] += a.w * b.x; acc[3][1] += a.w * b.y;
            acc[3][2] += a.w * b.z; acc[3][3] += a.w * b.w;
        }
        __syncthreads();
    }
    #pragma unroll
    for (int i = 0; i < 4; i++) {
        *(float4*)&g_Wh[(size_t)(mbase + ty * 4 + i) * NF + nbase + tx * 4] =
            make_float4(acc[i][0], acc[i][1], acc[i][2], acc[i][3]);
    }
}

// ---------------- s1/s2 for the 8-head stage ----------------------------------
__global__ void sheads_kernel(const float* __restrict__ aheads, int l) {
    int w = threadIdx.x >> 5, lane = threadIdx.x & 31;
    int row = blockIdx.x * 8 + w;          // b*NN + n
    int b = row >> 11, n = row & (NN - 1);
    #pragma unroll
    for (int h = 0; h < NH; h++) {
        float v  = g_Wh[(size_t)row * NF + h * NO + lane];
        float a1 = aheads[((size_t)l * NH + h) * 2 * NO + lane];
        float a2 = aheads[((size_t)l * NH + h) * 2 * NO + NO + lane];
        float p1 = v * a1, p2 = v * a2;
        #pragma unroll
        for (int off = 16; off; off >>= 1) {
            p1 += __shfl_xor_sync(0xffffffffu, p1, off);
            p2 += __shfl_xor_sync(0xffffffffu, p2, off);
        }
        if (lane == 0) {
            g_s1[(b * NH + h) * NN + n] = p1;
            g_s2[(b * NH + h) * NN + n] = p2;
        }
    }
}

// ---------------- s1/s2 for the single-head out stage -------------------------
__global__ void sout_kernel(const float* __restrict__ aout, int l) {
    int w = threadIdx.x >> 5, lane = threadIdx.x & 31;
    int row = blockIdx.x * 8 + w;          // b*NN + n
    float p1 = 0.f, p2 = 0.f;
    #pragma unroll
    for (int k = 0; k < NF / 32; k++) {
        float v = g_Wh[(size_t)row * NF + k * 32 + lane];
        p1 += v * aout[(size_t)l * 2 * NF + k * 32 + lane];
        p2 += v * aout[(size_t)l * 2 * NF + NF + k * 32 + lane];
    }
    #pragma unroll
    for (int off = 16; off; off >>= 1) {
        p1 += __shfl_xor_sync(0xffffffffu, p1, off);
        p2 += __shfl_xor_sync(0xffffffffu, p2, off);
    }
    if (lane == 0) { g_s1[row] = p1; g_s2[row] = p2; }
}

// ---------------- fused attention v8: lane = row, p in registers --------------
// Block = 32 rows x 1 head-chunk; 8 warps split the j range (each warp: per
// 128-j tile, a 16-j span at jloc0). Per j: p computed in-register per lane
// (lane = row), V[j][0..31] read as 8 broadcast LDS.128 shared by all 32 rows.
// No ps smem, no pk broadcasts, no V transpose. End: cross-warp reduction of
// acc (swizzled, aliased onto V buffers) + lsum.
#define JT  128
#define AW  8

__global__ void __launch_bounds__(256)
attn_kernel(float* __restrict__ oext, int osel,
            int spb, int symul, int elu2) {
    __shared__ __align__(16) float VT[2][JT * NO];   // 2 x 16KB, [buf][j*32+o]
    __shared__ __align__(16) float s2s[NN];          // 8KB
    __shared__ float redl[AW][32];
    __shared__ float redm[AW];

    float* out = (osel == 0) ? g_hA : (osel == 1 ? g_h : oext);
    int b = blockIdx.z, y = blockIdx.y;
    int tid = threadIdx.x;
    int w = tid >> 5, lane = tid & 31;
    int vb = y * NO;
    int sidx = b * spb + y * symul;
    const float* s1p = g_s1 + (size_t)sidx * NN;
    const float* s2p = g_s2 + (size_t)sidx * NN;
    int row0 = blockIdx.x * 32;
    int row  = row0 + lane;
    const float* Vg = g_Wh + ((size_t)b * NN) * NF + vb;

    // ---- prologue: async-load full s2 row (8KB) + V tile 0 ----
    #pragma unroll
    for (int k = 0; k < 2; k++) {
        int q = tid + 256 * k;
        cp16(&s2s[q * 4], s2p + q * 4);
    }
    #pragma unroll
    for (int k = 0; k < 4; k++) {
        int q = tid + 256 * k, j = q >> 3, seg = q & 7;
        cp16(&VT[0][j * NO + seg * 4], Vg + (size_t)j * NF + seg * 4);
    }
    CP_COMMIT();
    const unsigned* bmrow = g_bm + ((size_t)(b * NN + row) << 6) + (w & 3);
    unsigned mwcur = __ldg(bmrow);
    float s1r = s1p[row];
    CP_WAIT0();
    __syncthreads();

    // ---- fused m2 (block max of s2; any upper bound is valid) ----
    float mloc = -3.0e38f;
    for (int i = tid; i < NN; i += 256) mloc = fmaxf(mloc, s2s[i]);
    #pragma unroll
    for (int off = 16; off; off >>= 1)
        mloc = fmaxf(mloc, __shfl_xor_sync(0xffffffffu, mloc, off));
    if (lane == 0) redm[w] = mloc;
    __syncthreads();
    float m2 = redm[0];
    #pragma unroll
    for (int i = 1; i < AW; i++) m2 = fmaxf(m2, redm[i]);

    float t0 = s1r + m2;
    float cir = fmaxf(t0, 0.2f * t0);
    float lsum = 0.f;
    ull acc2[16];
    #pragma unroll
    for (int q = 0; q < 16; q++) acc2[q] = 0ull;

    int jhalf = (w >> 2) * 16;
    int jloc0 = (w & 3) * 32 + jhalf;    // within-tile j base for this warp

    for (int it = 0; it < NN / JT; it++) {
        int buf = it & 1;
        unsigned mw = mwcur;
        if (it + 1 < NN / JT) {          // prefetch next tile + next mask word
            const float* Vn = Vg + (size_t)(it + 1) * JT * NF;
            #pragma unroll
            for (int k = 0; k < 4; k++) {
                int q = tid + 256 * k, j = q >> 3, seg = q & 7;
                cp16(&VT[buf ^ 1][j * NO + seg * 4], Vn + (size_t)j * NF + seg * 4);
            }
            CP_COMMIT();
            mwcur = __ldg(bmrow + (it + 1) * 4);
            CP_WAIT1();
        } else {
            CP_WAIT0();
        }
        __syncthreads();

        const float* s2b = s2s + it * JT + jloc0;
        const char* vrow0 = (const char*)&VT[buf][jloc0 * NO];
        #pragma unroll
        for (int jj = 0; jj < 16; jj++) {
            float x = s1r + s2b[jj];
            float e = fmaxf(x, 0.2f * x);                // leakyrelu(0.2)
            float p = ((mw >> (jhalf + jj)) & 1u) ? __expf(e - cir) : 0.f;
            lsum += p;
            ull pp = pack2(p, p);
            const ulonglong2* vr = (const ulonglong2*)(vrow0 + jj * 128);
            #pragma unroll
            for (int q4 = 0; q4 < 8; q4++) {
                ulonglong2 vv = vr[q4];                  // broadcast LDS.128
                ffma2(acc2[2 * q4],     pp, vv.x);
                ffma2(acc2[2 * q4 + 1], pp, vv.y);
            }
        }
        __syncthreads();
    }

    // ---- cross-warp reduction (acc partials aliased onto VT; swizzled) ----
    ull* red = (ull*)&VT[0][0];          // 8*32*16 ull = 32KB = both V buffers
    {
        ull* my = red + ((size_t)w * 32 + lane) * 16;
        #pragma unroll
        for (int q4 = 0; q4 < 8; q4++) {
            int pidx = (q4 + lane) & 7;
            *(ulonglong2*)(my + pidx * 2) =
                make_ulonglong2(acc2[2 * q4], acc2[2 * q4 + 1]);
        }
        redl[w][lane] = lsum;
    }
    __syncthreads();
    {
        int orow = tid >> 3, q4r = tid & 7;
        int pidx = (q4r + orow) & 7;
        ull a0 = 0ull, a1 = 0ull;
        #pragma unroll
        for (int ww = 0; ww < AW; ww++) {
            ulonglong2 vv = *(const ulonglong2*)
                (red + ((size_t)ww * 32 + orow) * 16 + pidx * 2);
            fadd2(a0, vv.x);
            fadd2(a1, vv.y);
        }
        float l = 0.f;
        #pragma unroll
        for (int ww = 0; ww < AW; ww++) l += redl[ww][orow];
        float inv = 1.0f / l;
        float2 p0 = unpack2(a0), p1 = unpack2(a1);
        float v[4] = {p0.x * inv, p0.y * inv, p1.x * inv, p1.y * inv};
        #pragma unroll
        for (int k = 0; k < 4; k++) {
            float vv = v[k];
            vv = (vv > 0.f) ? vv : (__expf(vv) - 1.f);           // elu
            if (elu2) vv = (vv > 0.f) ? vv : (__expf(vv) - 1.f); // second elu
            v[k] = vv;
        }
        *(float4*)&out[((size_t)(b * NN + row0 + orow)) * NF + vb + q4r * 4] =
            make_float4(v[0], v[1], v[2], v[3]);
    }
}

// ---------------- launch ------------------------------------------------------
extern "C" void kernel_launch(void* const* d_in, const int* in_sizes, int n_in,
                              void* d_out, int out_size) {
    const float* x       = (const float*)d_in[0];
    const int*   adj     = (const int*)  d_in[1];
    const float* W_heads = (const float*)d_in[2];
    const float* a_heads = (const float*)d_in[3];
    const float* W_out   = (const float*)d_in[4];
    const float* a_out   = (const float*)d_in[5];
    float* out = (float*)d_out;

    for (int l = 0; l < 3; l++) {
        // ---- stage A: 8-head GAT ----
        gemm_kernel<<<dim3(4, NB * NN / 64), 256>>>(
            l == 0 ? x : nullptr, W_heads + (size_t)l * NH * NF * NO,
            l == 0 ? 0 : 1, 0);
        sheads_kernel<<<NB * NN / 8, 256>>>(a_heads, l);
        if (l == 0) bm_kernel<<<NB * NN * 64 / 8, 256>>>(adj);
        attn_kernel<<<dim3(NN / 32, 8, NB), 256>>>(nullptr, 0, NH, 1, 0);

        // ---- stage B: single-head out GAT (+extra elu) ----
        gemm_kernel<<<dim3(4, NB * NN / 64), 256>>>(
            nullptr, W_out + (size_t)l * NF * NF, 2, 1);
        sout_kernel<<<NB * NN / 8, 256>>>(a_out, l);
        attn_kernel<<<dim3(NN / 32, 8, NB), 256>>>(
            l == 2 ? out : nullptr, l == 2 ? 2 : 1, 1, 0, 1);
    }
}

// round 15
// speedup vs baseline: 1.3168x; 1.2322x over previous
#include <cuda_runtime.h>
#include <cuda_bf16.h>

#define NB 2
#define NN 2048
#define NF 256
#define NH 8
#define NO 32

typedef unsigned long long ull;

// ---------------- f32x2 packed-math helpers (sm_103a FFMA2 path) --------------
__device__ __forceinline__ void ffma2(ull& d, ull a, ull b) {
    asm("fma.rn.f32x2 %0, %1, %2, %0;" : "+l"(d) : "l"(a), "l"(b));
}
__device__ __forceinline__ void fadd2(ull& d, ull a) {
    asm("add.rn.f32x2 %0, %1, %0;" : "+l"(d) : "l"(a));
}
__device__ __forceinline__ ull pack2(float x, float y) {
    ull r;
    asm("mov.b64 %0, {%1, %2};" : "=l"(r) : "f"(x), "f"(y));
    return r;
}
__device__ __forceinline__ float2 unpack2(ull v) {
    float2 r;
    asm("mov.b64 {%0, %1}, %2;" : "=f"(r.x), "=f"(r.y) : "l"(v));
    return r;
}

// ---------------- cp.async helpers --------------------------------------------
__device__ __forceinline__ void cp16(const void* smem_dst, const void* gsrc) {
    unsigned d = (unsigned)__cvta_generic_to_shared(smem_dst);
    asm volatile("cp.async.cg.shared.global [%0], [%1], 16;" :: "r"(d), "l"(gsrc));
}
#define CP_COMMIT() asm volatile("cp.async.commit_group;")
#define CP_WAIT0()  asm volatile("cp.async.wait_group 0;")
#define CP_WAIT1()  asm volatile("cp.async.wait_group 1;")

// ---------------- scratch (device globals; no allocation allowed) -------------
__device__ __align__(128) float    g_h [NB*NN*NF];   // layer input / stage-B output
__device__ __align__(128) float    g_hA[NB*NN*NF];   // stage-A attention output
__device__ __align__(128) float    g_Wh[NB*NN*NF];   // projected features (V), row-major
__device__ __align__(128) float    g_s1[NB*NH*NN];
__device__ __align__(128) float    g_s2[NB*NH*NN];
__device__ __align__(128) unsigned g_bm[NB*NN*(NN/32)];  // adjacency bitmask

// ---------------- adjacency -> bitmask (runs once) ----------------------------
__global__ void bm_kernel(const int* __restrict__ adj) {
    int wid  = blockIdx.x * 8 + (threadIdx.x >> 5);
    int lane = threadIdx.x & 31;
    int word = wid & 63;
    int row  = wid >> 6;                       // b*NN + i
    int j = word * 32 + lane;
    int a = adj[(size_t)row * NN + j];
    unsigned bits = __ballot_sync(0xffffffffu, a != 0);
    if (lane == 0) g_bm[wid] = bits;
}

// ---------------- GEMM: g_Wh = A[M,256] @ B[256,256] --------------------------
// asel: 0 -> Aext (x), 1 -> g_h, 2 -> g_hA
// bmode 0: B = W_heads[l] head-packed on the fly; bmode 1: B = Bsrc (plain)
__global__ void gemm_kernel(const float* __restrict__ Aext,
                            const float* __restrict__ Bsrc,
                            int asel, int bmode) {
    const float* A = (asel == 0) ? Aext : (asel == 1 ? g_h : g_hA);
    __shared__ __align__(16) float Ast[16][68];   // [k][m], padded
    __shared__ __align__(16) float Bs [16][64];   // [k][n]
    int tid = threadIdx.x;
    int tx = tid & 15, ty = tid >> 4;
    int mbase = blockIdx.y * 64, nbase = blockIdx.x * 64;
    float acc[4][4];
    #pragma unroll
    for (int i = 0; i < 4; i++)
        #pragma unroll
        for (int j = 0; j < 4; j++) acc[i][j] = 0.f;

    int am = tid >> 2, ak = (tid & 3) * 4;
    int bk = tid >> 4, bn = (tid & 15) * 4;
    int c0 = nbase + bn, hh = c0 >> 5, cc = c0 & 31;

    for (int kk = 0; kk < NF; kk += 16) {
        float4 av = *(const float4*)&A[(size_t)(mbase + am) * NF + kk + ak];
        float4 bv;
        if (bmode == 0)   // W_heads[l][h][f][o] with h=c>>5, o=c&31 (cc mult of 4)
            bv = *(const float4*)&Bsrc[((size_t)hh * NF + kk + bk) * NO + cc];
        else
            bv = *(const float4*)&Bsrc[(size_t)(kk + bk) * NF + c0];
        Ast[ak + 0][am] = av.x; Ast[ak + 1][am] = av.y;
        Ast[ak + 2][am] = av.z; Ast[ak + 3][am] = av.w;
        *(float4*)&Bs[bk][bn] = bv;
        __syncthreads();
        #pragma unroll
        for (int k = 0; k < 16; k++) {
            float4 a = *(const float4*)&Ast[k][ty * 4];
            float4 b = *(const float4*)&Bs [k][tx * 4];
            acc[0][0] += a.x * b.x; acc[0][1] += a.x * b.y;
            acc[0][2] += a.x * b.z; acc[0][3] += a.x * b.w;
            acc[1][0] += a.y * b.x; acc[1][1] += a.y * b.y;
            acc[1][2] += a.y * b.z; acc[1][3] += a.y * b.w;
            acc[2][0] += a.z * b.x; acc[2][1] += a.z * b.y;
            acc[2][2] += a.z * b.z; acc[2][3] += a.z * b.w;
            acc[3][0] += a.w * b.x; acc[3][1] += a.w * b.y;
            acc[3][2] += a.w * b.z; acc[3][3] += a.w * b.w;
        }
        __syncthreads();
    }
    #pragma unroll
    for (int i = 0; i < 4; i++) {
        *(float4*)&g_Wh[(size_t)(mbase + ty * 4 + i) * NF + nbase + tx * 4] =
            make_float4(acc[i][0], acc[i][1], acc[i][2], acc[i][3]);
    }
}

// ---------------- s1/s2 for the 8-head stage ----------------------------------
__global__ void sheads_kernel(const float* __restrict__ aheads, int l) {
    int w = threadIdx.x >> 5, lane = threadIdx.x & 31;
    int row = blockIdx.x * 8 + w;          // b*NN + n
    int b = row >> 11, n = row & (NN - 1);
    #pragma unroll
    for (int h = 0; h < NH; h++) {
        float v  = g_Wh[(size_t)row * NF + h * NO + lane];
        float a1 = aheads[((size_t)l * NH + h) * 2 * NO + lane];
        float a2 = aheads[((size_t)l * NH + h) * 2 * NO + NO + lane];
        float p1 = v * a1, p2 = v * a2;
        #pragma unroll
        for (int off = 16; off; off >>= 1) {
            p1 += __shfl_xor_sync(0xffffffffu, p1, off);
            p2 += __shfl_xor_sync(0xffffffffu, p2, off);
        }
        if (lane == 0) {
            g_s1[(b * NH + h) * NN + n] = p1;
            g_s2[(b * NH + h) * NN + n] = p2;
        }
    }
}

// ---------------- s1/s2 for the single-head out stage -------------------------
__global__ void sout_kernel(const float* __restrict__ aout, int l) {
    int w = threadIdx.x >> 5, lane = threadIdx.x & 31;
    int row = blockIdx.x * 8 + w;          // b*NN + n
    float p1 = 0.f, p2 = 0.f;
    #pragma unroll
    for (int k = 0; k < NF / 32; k++) {
        float v = g_Wh[(size_t)row * NF + k * 32 + lane];
        p1 += v * aout[(size_t)l * 2 * NF + k * 32 + lane];
        p2 += v * aout[(size_t)l * 2 * NF + NF + k * 32 + lane];
    }
    #pragma unroll
    for (int off = 16; off; off >>= 1) {
        p1 += __shfl_xor_sync(0xffffffffu, p1, off);
        p2 += __shfl_xor_sync(0xffffffffu, p2, off);
    }
    if (lane == 0) { g_s1[row] = p1; g_s2[row] = p2; }
}

// ---------------- fused attention v9: lane = 2 rows, p in registers -----------
// Block = 64 rows x 1 head-chunk; 8 warps split the j range (16-j span each).
// Lane carries TWO rows (row0+lane, row0+32+lane): every broadcast V LDS.128
// and s2 load is amortized over 2 rows -> crossbar 1152 << fma 2048 cyc/tile.
// Epilogue: two 32-row reduction passes over the VT-aliased 32KB buffer.
#define JT  128
#define AW  8

__global__ void __launch_bounds__(256, 2)
attn_kernel(float* __restrict__ oext, int osel,
            int spb, int symul, int elu2) {
    __shared__ __align__(16) float VT[2][JT * NO];   // 2 x 16KB, [buf][j*32+o]
    __shared__ __align__(16) float s2s[NN];          // 8KB
    __shared__ float redl[2][AW][32];
    __shared__ float redm[AW];

    float* out = (osel == 0) ? g_hA : (osel == 1 ? g_h : oext);
    int b = blockIdx.z, y = blockIdx.y;
    int tid = threadIdx.x;
    int w = tid >> 5, lane = tid & 31;
    int vb = y * NO;
    int sidx = b * spb + y * symul;
    const float* s1p = g_s1 + (size_t)sidx * NN;
    const float* s2p = g_s2 + (size_t)sidx * NN;
    int row0 = blockIdx.x * 64;
    int rowA = row0 + lane, rowB = row0 + 32 + lane;
    const float* Vg = g_Wh + ((size_t)b * NN) * NF + vb;

    // ---- prologue: async-load full s2 row (8KB) + V tile 0 ----
    #pragma unroll
    for (int k = 0; k < 2; k++) {
        int q = tid + 256 * k;
        cp16(&s2s[q * 4], s2p + q * 4);
    }
    #pragma unroll
    for (int k = 0; k < 4; k++) {
        int q = tid + 256 * k, j = q >> 3, seg = q & 7;
        cp16(&VT[0][j * NO + seg * 4], Vg + (size_t)j * NF + seg * 4);
    }
    CP_COMMIT();
    const unsigned* bmrowA = g_bm + ((size_t)(b * NN + rowA) << 6) + (w & 3);
    const unsigned* bmrowB = g_bm + ((size_t)(b * NN + rowB) << 6) + (w & 3);
    unsigned mwcurA = __ldg(bmrowA), mwcurB = __ldg(bmrowB);
    float s1A = s1p[rowA], s1B = s1p[rowB];
    CP_WAIT0();
    __syncthreads();

    // ---- fused m2 (block max of s2; any upper bound is valid) ----
    float mloc = -3.0e38f;
    for (int i = tid; i < NN; i += 256) mloc = fmaxf(mloc, s2s[i]);
    #pragma unroll
    for (int off = 16; off; off >>= 1)
        mloc = fmaxf(mloc, __shfl_xor_sync(0xffffffffu, mloc, off));
    if (lane == 0) redm[w] = mloc;
    __syncthreads();
    float m2 = redm[0];
    #pragma unroll
    for (int i = 1; i < AW; i++) m2 = fmaxf(m2, redm[i]);

    float tA = s1A + m2, tB = s1B + m2;
    float cirA = fmaxf(tA, 0.2f * tA), cirB = fmaxf(tB, 0.2f * tB);
    float lsumA = 0.f, lsumB = 0.f;
    ull accA[16], accB[16];
    #pragma unroll
    for (int q = 0; q < 16; q++) { accA[q] = 0ull; accB[q] = 0ull; }

    int jhalf = (w >> 2) * 16;
    int jloc0 = (w & 3) * 32 + jhalf;    // within-tile j base for this warp

    for (int it = 0; it < NN / JT; it++) {
        int buf = it & 1;
        unsigned mwA = mwcurA, mwB = mwcurB;
        if (it + 1 < NN / JT) {          // prefetch next tile + next mask words
            const float* Vn = Vg + (size_t)(it + 1) * JT * NF;
            #pragma unroll
            for (int k = 0; k < 4; k++) {
                int q = tid + 256 * k, j = q >> 3, seg = q & 7;
                cp16(&VT[buf ^ 1][j * NO + seg * 4], Vn + (size_t)j * NF + seg * 4);
            }
            CP_COMMIT();
            mwcurA = __ldg(bmrowA + (it + 1) * 4);
            mwcurB = __ldg(bmrowB + (it + 1) * 4);
            CP_WAIT1();
        } else {
            CP_WAIT0();
        }
        __syncthreads();

        const float* s2b = s2s + it * JT + jloc0;
        const char* vrow0 = (const char*)&VT[buf][jloc0 * NO];
        #pragma unroll
        for (int jj = 0; jj < 16; jj++) {
            float s2v = s2b[jj];
            float xA = s1A + s2v, xB = s1B + s2v;
            float eA = fmaxf(xA, 0.2f * xA);             // leakyrelu(0.2)
            float eB = fmaxf(xB, 0.2f * xB);
            float pA = ((mwA >> (jhalf + jj)) & 1u) ? __expf(eA - cirA) : 0.f;
            float pB = ((mwB >> (jhalf + jj)) & 1u) ? __expf(eB - cirB) : 0.f;
            lsumA += pA; lsumB += pB;
            ull ppA = pack2(pA, pA), ppB = pack2(pB, pB);
            const ulonglong2* vr = (const ulonglong2*)(vrow0 + jj * 128);
            #pragma unroll
            for (int q4 = 0; q4 < 8; q4++) {
                ulonglong2 vv = vr[q4];                  // broadcast LDS.128
                ffma2(accA[2 * q4],     ppA, vv.x);
                ffma2(accA[2 * q4 + 1], ppA, vv.y);
                ffma2(accB[2 * q4],     ppB, vv.x);
                ffma2(accB[2 * q4 + 1], ppB, vv.y);
            }
        }
        __syncthreads();
    }

    redl[0][w][lane] = lsumA;
    redl[1][w][lane] = lsumB;

    // ---- cross-warp reduction: two 32-row passes over VT-aliased buffer ----
    ull* red = (ull*)&VT[0][0];          // 8*32*16 ull = 32KB = both V buffers
    #pragma unroll
    for (int r = 0; r < 2; r++) {
        ull* my = red + ((size_t)w * 32 + lane) * 16;
        #pragma unroll
        for (int q4 = 0; q4 < 8; q4++) {
            int pidx = (q4 + lane) & 7;
            ull lo = r ? accB[2 * q4]     : accA[2 * q4];
            ull hi = r ? accB[2 * q4 + 1] : accA[2 * q4 + 1];
            *(ulonglong2*)(my + pidx * 2) = make_ulonglong2(lo, hi);
        }
        __syncthreads();
        {
            int orow = tid >> 3, q4r = tid & 7;
            int pidx = (q4r + orow) & 7;
            ull a0 = 0ull, a1 = 0ull;
            #pragma unroll
            for (int ww = 0; ww < AW; ww++) {
                ulonglong2 vv = *(const ulonglong2*)
                    (red + ((size_t)ww * 32 + orow) * 16 + pidx * 2);
                fadd2(a0, vv.x);
                fadd2(a1, vv.y);
            }
            float l = 0.f;
            #pragma unroll
            for (int ww = 0; ww < AW; ww++) l += redl[r][ww][orow];
            float inv = 1.0f / l;
            float2 p0 = unpack2(a0), p1 = unpack2(a1);
            float v[4] = {p0.x * inv, p0.y * inv, p1.x * inv, p1.y * inv};
            #pragma unroll
            for (int k = 0; k < 4; k++) {
                float vv = v[k];
                vv = (vv > 0.f) ? vv : (__expf(vv) - 1.f);           // elu
                if (elu2) vv = (vv > 0.f) ? vv : (__expf(vv) - 1.f); // 2nd elu
                v[k] = vv;
            }
            *(float4*)&out[((size_t)(b * NN + row0 + r * 32 + orow)) * NF
                           + vb + q4r * 4] =
                make_float4(v[0], v[1], v[2], v[3]);
        }
        if (r == 0) __syncthreads();
    }
}

// ---------------- launch ------------------------------------------------------
extern "C" void kernel_launch(void* const* d_in, const int* in_sizes, int n_in,
                              void* d_out, int out_size) {
    const float* x       = (const float*)d_in[0];
    const int*   adj     = (const int*)  d_in[1];
    const float* W_heads = (const float*)d_in[2];
    const float* a_heads = (const float*)d_in[3];
    const float* W_out   = (const float*)d_in[4];
    const float* a_out   = (const float*)d_in[5];
    float* out = (float*)d_out;

    for (int l = 0; l < 3; l++) {
        // ---- stage A: 8-head GAT ----
        gemm_kernel<<<dim3(4, NB * NN / 64), 256>>>(
            l == 0 ? x : nullptr, W_heads + (size_t)l * NH * NF * NO,
            l == 0 ? 0 : 1, 0);
        sheads_kernel<<<NB * NN / 8, 256>>>(a_heads, l);
        if (l == 0) bm_kernel<<<NB * NN * 64 / 8, 256>>>(adj);
        attn_kernel<<<dim3(NN / 64, 8, NB), 256>>>(nullptr, 0, NH, 1, 0);

        // ---- stage B: single-head out GAT (+extra elu) ----
        gemm_kernel<<<dim3(4, NB * NN / 64), 256>>>(
            nullptr, W_out + (size_t)l * NF * NF, 2, 1);
        sout_kernel<<<NB * NN / 8, 256>>>(a_out, l);
        attn_kernel<<<dim3(NN / 64, 8, NB), 256>>>(
            l == 2 ? out : nullptr, l == 2 ? 2 : 1, 1, 0, 1);
    }
}